// round 1
// baseline (speedup 1.0000x reference)
#include <cuda_runtime.h>

#define TPB 256

// ---------------------------------------------------------------------------
// 4-qubit real statevector helpers. Wire 0 is the MOST significant bit
// (reference reshapes to (B,2,2,2,2) with wire w on axis w+1).
// All indices are compile-time constants -> CNOT = pure register rename.
// ---------------------------------------------------------------------------
template <int W>
__device__ __forceinline__ void ry_gate(float* psi, float c, float s) {
    const int bit = 8 >> W;
#pragma unroll
    for (int i = 0; i < 16; i++) {
        if ((i & bit) == 0) {
            const int j = i | bit;
            float a = psi[i], b = psi[j];
            psi[i] = fmaf(c, a, -s * b);
            psi[j] = fmaf(s, a, c * b);
        }
    }
}

template <int CTRL, int TGT>
__device__ __forceinline__ void cnot_gate(float* psi) {
    const int cb = 8 >> CTRL, tb = 8 >> TGT;
#pragma unroll
    for (int i = 0; i < 16; i++) {
        if ((i & cb) && !(i & tb)) {
            const int j = i | tb;
            float t = psi[i];
            psi[i] = psi[j];
            psi[j] = t;
        }
    }
}

__global__ __launch_bounds__(TPB) void qnet_kernel(
    const float* __restrict__ state,  // (B,64)
    const float* __restrict__ W1,     // (32,64)
    const float* __restrict__ b1,     // (32)
    const float* __restrict__ W2,     // (4,32)
    const float* __restrict__ b2,     // (4)
    const float* __restrict__ qp,     // (8)
    const float* __restrict__ H1,     // (32,4)
    const float* __restrict__ c1,     // (32)
    const float* __restrict__ H2,     // (16,32)
    const float* __restrict__ c2,     // (16)
    float* __restrict__ out,          // (B,16)
    int B)
{
    // ---- shared weights -------------------------------------------------
    __shared__ float sW1t[64 * 32];   // transposed: [k][j]
    __shared__ float sW2[4 * 32];
    __shared__ float sH1[32 * 4];
    __shared__ float sH2[16 * 32];
    __shared__ float sb1[32], sc1[32], sc2[16];
    __shared__ float sb2[4];
    __shared__ float sqc[8], sqs[8];

    const int tid = threadIdx.x;

    // W1 transpose into smem (coalesced gmem reads)
#pragma unroll
    for (int i = tid; i < 2048; i += TPB) {
        int j = i >> 6, k = i & 63;
        sW1t[k * 32 + j] = W1[i];
    }
    if (tid < 128) sW2[tid] = W2[tid];
    if (tid < 128) sH1[tid] = H1[tid];
#pragma unroll
    for (int i = tid; i < 512; i += TPB) sH2[i] = H2[i];
    if (tid < 32) sb1[tid] = b1[tid];
    if (tid < 32) sc1[tid] = c1[tid];
    if (tid < 16) sc2[tid] = c2[tid];
    if (tid < 4)  sb2[tid] = b2[tid];
    if (tid < 8) {
        float cc, ss;
        sincosf(0.5f * qp[tid], &ss, &cc);
        sqc[tid] = cc;
        sqs[tid] = ss;
    }
    __syncthreads();

    const int b = blockIdx.x * TPB + tid;
    if (b >= B) return;

    // ---- layer 1: h = relu(x @ W1^T + b1) -------------------------------
    float h[32];
#pragma unroll
    for (int j = 0; j < 32; j++) h[j] = sb1[j];

    const float4* __restrict__ xp = reinterpret_cast<const float4*>(state) + (size_t)b * 16;
    const float4* __restrict__ w1 = reinterpret_cast<const float4*>(sW1t);
#pragma unroll
    for (int k4 = 0; k4 < 16; k4++) {
        float4 xv = xp[k4];
        float xk[4] = {xv.x, xv.y, xv.z, xv.w};
#pragma unroll
        for (int kk = 0; kk < 4; kk++) {
            const int k = k4 * 4 + kk;
#pragma unroll
            for (int j4 = 0; j4 < 8; j4++) {
                float4 w = w1[k * 8 + j4];
                h[j4 * 4 + 0] = fmaf(xk[kk], w.x, h[j4 * 4 + 0]);
                h[j4 * 4 + 1] = fmaf(xk[kk], w.y, h[j4 * 4 + 1]);
                h[j4 * 4 + 2] = fmaf(xk[kk], w.z, h[j4 * 4 + 2]);
                h[j4 * 4 + 3] = fmaf(xk[kk], w.w, h[j4 * 4 + 3]);
            }
        }
    }
#pragma unroll
    for (int j = 0; j < 32; j++) h[j] = fmaxf(h[j], 0.0f);

    // ---- layer 2: encoded = tanh(h @ W2^T + b2), then half-angles -------
    float ec[4], es[4];
#pragma unroll
    for (int i = 0; i < 4; i++) {
        float acc = sb2[i];
        const float4* w2 = reinterpret_cast<const float4*>(sW2 + i * 32);
#pragma unroll
        for (int j4 = 0; j4 < 8; j4++) {
            float4 w = w2[j4];
            acc = fmaf(h[j4 * 4 + 0], w.x, acc);
            acc = fmaf(h[j4 * 4 + 1], w.y, acc);
            acc = fmaf(h[j4 * 4 + 2], w.z, acc);
            acc = fmaf(h[j4 * 4 + 3], w.w, acc);
        }
        float e = tanhf(acc);
        __sincosf(0.5f * e, &es[i], &ec[i]);
    }

    // ---- encoding RYs from |0000> == product state ----------------------
    float A[4] = {ec[0] * ec[1], ec[0] * es[1], es[0] * ec[1], es[0] * es[1]};
    float C[4] = {ec[2] * ec[3], ec[2] * es[3], es[2] * ec[3], es[2] * es[3]};
    float psi[16];
#pragma unroll
    for (int hi = 0; hi < 4; hi++)
#pragma unroll
        for (int lo = 0; lo < 4; lo++)
            psi[hi * 4 + lo] = A[hi] * C[lo];

    // ---- entangling layers ----------------------------------------------
#pragma unroll
    for (int layer = 0; layer < 2; layer++) {
        cnot_gate<0, 1>(psi);
        cnot_gate<1, 2>(psi);
        cnot_gate<2, 3>(psi);
        cnot_gate<3, 0>(psi);
        const int o = layer * 4;
        ry_gate<0>(psi, sqc[o + 0], sqs[o + 0]);
        ry_gate<1>(psi, sqc[o + 1], sqs[o + 1]);
        ry_gate<2>(psi, sqc[o + 2], sqs[o + 2]);
        ry_gate<3>(psi, sqc[o + 3], sqs[o + 3]);
    }

    // ---- Pauli-Z expectations --------------------------------------------
    float p[16];
#pragma unroll
    for (int i = 0; i < 16; i++) p[i] = psi[i] * psi[i];
    float z[4];
#pragma unroll
    for (int w = 0; w < 4; w++) {
        const int bit = 8 >> w;
        float acc = 0.0f;
#pragma unroll
        for (int i = 0; i < 16; i++) acc += (i & bit) ? -p[i] : p[i];
        z[w] = acc;
    }

    // ---- head: h2 = relu(z @ H1^T + c1) ----------------------------------
    float h2[32];
#pragma unroll
    for (int o = 0; o < 32; o++) {
        float4 w = reinterpret_cast<const float4*>(sH1)[o];
        float acc = sc1[o];
        acc = fmaf(z[0], w.x, acc);
        acc = fmaf(z[1], w.y, acc);
        acc = fmaf(z[2], w.z, acc);
        acc = fmaf(z[3], w.w, acc);
        h2[o] = fmaxf(acc, 0.0f);
    }

    // ---- out = tanh(h2 @ H2^T + c2) --------------------------------------
    float res[16];
#pragma unroll
    for (int o = 0; o < 16; o++) {
        float acc = sc2[o];
        const float4* w2 = reinterpret_cast<const float4*>(sH2 + o * 32);
#pragma unroll
        for (int j4 = 0; j4 < 8; j4++) {
            float4 w = w2[j4];
            acc = fmaf(h2[j4 * 4 + 0], w.x, acc);
            acc = fmaf(h2[j4 * 4 + 1], w.y, acc);
            acc = fmaf(h2[j4 * 4 + 2], w.z, acc);
            acc = fmaf(h2[j4 * 4 + 3], w.w, acc);
        }
        res[o] = tanhf(acc);
    }

    float4* o4 = reinterpret_cast<float4*>(out) + (size_t)b * 4;
#pragma unroll
    for (int t = 0; t < 4; t++)
        o4[t] = make_float4(res[t * 4 + 0], res[t * 4 + 1], res[t * 4 + 2], res[t * 4 + 3]);
}

extern "C" void kernel_launch(void* const* d_in, const int* in_sizes, int n_in,
                              void* d_out, int out_size) {
    const float* state = (const float*)d_in[0];
    const float* W1    = (const float*)d_in[1];
    const float* b1    = (const float*)d_in[2];
    const float* W2    = (const float*)d_in[3];
    const float* b2    = (const float*)d_in[4];
    const float* qp    = (const float*)d_in[5];
    const float* H1    = (const float*)d_in[6];
    const float* c1    = (const float*)d_in[7];
    const float* H2    = (const float*)d_in[8];
    const float* c2    = (const float*)d_in[9];

    const int B = in_sizes[0] / 64;
    const int grid = (B + TPB - 1) / TPB;
    qnet_kernel<<<grid, TPB>>>(state, W1, b1, W2, b2, qp, H1, c1, H2, c2,
                               (float*)d_out, B);
}